// round 16
// baseline (speedup 1.0000x reference)
#include <cuda_runtime.h>
#include <cuda_bf16.h>
#include <cstdint>

// ---------------------------------------------------------------------------
// Problem constants
// ---------------------------------------------------------------------------
#define HH   56
#define WWID 56
#define DDEP 28
#define LTOK 87808          // 56*56*28
#define CDIM 96
#define NWIN 256
#define NTOK 343
#define NHEAD 3
#define FF   384
#define BN   96             // GEMM N tile
#define BM   128            // GEMM M tile
#define LOG2E 1.4426950408889634f
#define SMAX 16.0f          // fixed softmax shift (log2 domain)

// ---------------------------------------------------------------------------
// Scratch (device globals; no allocation allowed)
// ---------------------------------------------------------------------------
__device__ __align__(16) float g_X  [(size_t)LTOK * CDIM];
__device__ int g_DST[LTOK];
// bf16 activations
__device__ __align__(16) __nv_bfloat16 g_QKVh[(size_t)LTOK * 288];
__device__ __align__(16) __nv_bfloat16 g_Hb [(size_t)LTOK * CDIM];
__device__ __align__(16) __nv_bfloat16 g_Ob [(size_t)LTOK * CDIM];
__device__ __align__(16) __nv_bfloat16 g_X2b[(size_t)LTOK * CDIM];
__device__ __align__(16) __nv_bfloat16 g_FFb[(size_t)LTOK * FF];
// bf16 pre-transposed weights [N,K]
__device__ __align__(16) __nv_bfloat16 g_WtQKVh [288 * 96];
__device__ __align__(16) __nv_bfloat16 g_WtPROJh[96 * 96];
__device__ __align__(16) __nv_bfloat16 g_WtFC1h [384 * 96];
__device__ __align__(16) __nv_bfloat16 g_WtFC2h [96 * 384];
// precomputed bias+mask table (log2-domain): [8 classes][3 heads][343][352]
#define SBROW 352
__device__ __align__(16) float g_SB[24 * NTOK * SBROW];

// ---------------------------------------------------------------------------
// helpers
// ---------------------------------------------------------------------------
__device__ __forceinline__ void mma16(float* c, const uint32_t* a, uint32_t b0, uint32_t b1) {
    asm("mma.sync.aligned.m16n8k16.row.col.f32.bf16.bf16.f32 "
        "{%0,%1,%2,%3}, {%4,%5,%6,%7}, {%8,%9}, {%0,%1,%2,%3};"
        : "+f"(c[0]), "+f"(c[1]), "+f"(c[2]), "+f"(c[3])
        : "r"(a[0]), "r"(a[1]), "r"(a[2]), "r"(a[3]), "r"(b0), "r"(b1));
}
__device__ __forceinline__ void ldsm4(uint32_t& r0, uint32_t& r1, uint32_t& r2, uint32_t& r3,
                                      uint32_t addr) {
    asm volatile("ldmatrix.sync.aligned.m8n8.x4.shared.b16 {%0,%1,%2,%3}, [%4];"
        : "=r"(r0), "=r"(r1), "=r"(r2), "=r"(r3) : "r"(addr));
}
__device__ __forceinline__ void ldsm4t(uint32_t& r0, uint32_t& r1, uint32_t& r2, uint32_t& r3,
                                       uint32_t addr) {
    asm volatile("ldmatrix.sync.aligned.m8n8.x4.trans.shared.b16 {%0,%1,%2,%3}, [%4];"
        : "=r"(r0), "=r"(r1), "=r"(r2), "=r"(r3) : "r"(addr));
}
__device__ __forceinline__ uint32_t bf2(float lo, float hi) {
    uint32_t d;
    asm("cvt.rn.bf16x2.f32 %0, %1, %2;" : "=r"(d) : "f"(hi), "f"(lo));
    return d;
}
__device__ __forceinline__ void cp16(uint32_t dst, const void* src) {
    asm volatile("cp.async.cg.shared.global [%0], [%1], 16;" :: "r"(dst), "l"(src));
}
__device__ __forceinline__ float ex2(float x) {
    float y;
    asm("ex2.approx.f32 %0, %1;" : "=f"(y) : "f"(x));
    return y;
}

// ---------------------------------------------------------------------------
// Prep: weight transposes + bias+mask table (log2 domain), one launch
// ---------------------------------------------------------------------------
__global__ void prep_kernel(const float* __restrict__ qkv_w,
                            const float* __restrict__ proj_w,
                            const float* __restrict__ fc1_w,
                            const float* __restrict__ fc2_w,
                            const float* __restrict__ rpb)
{
    int gid = blockIdx.x * 256 + threadIdx.x;

    if (gid < 110592) {
        int idx = gid;
        if (idx < 27648) {
            int k = idx / 288, n = idx - k * 288;
            g_WtQKVh[n * 96 + k] = __float2bfloat16(qkv_w[idx]);
        } else if (idx < 36864) {
            int j = idx - 27648;
            int k = j / 96, n = j - k * 96;
            g_WtPROJh[n * 96 + k] = __float2bfloat16(proj_w[j]);
        } else if (idx < 73728) {
            int j = idx - 36864;
            int k = j / 384, n = j - k * 384;
            g_WtFC1h[n * 96 + k] = __float2bfloat16(fc1_w[j]);
        } else {
            int j = idx - 73728;
            int k = j / 96, n = j - k * 96;
            g_WtFC2h[n * 384 + k] = __float2bfloat16(fc2_w[j]);
        }
    }

    if (gid < 24 * NTOK * SBROW) {
        int m  = gid % SBROW;
        int t  = gid / SBROW;
        int n  = t % NTOK;
        int ch = t / NTOK;
        int h  = ch % 3, cls = ch / 3;
        float v;
        if (m >= NTOK) {
            v = -30000.0f;
        } else {
            int an = n / 49, rn = n - an * 49, bn = rn / 7, cn = rn - bn * 7;
            int am = m / 49, rm = m - am * 49, bm = rm / 7, cm = rm - bm * 7;
            int sub_n = an * 169 + bn * 13 + cn;
            int sub_m = am * 169 + bm * 13 + cm;
            v = rpb[(1098 + sub_n - sub_m) * 3 + h] * LOG2E;
            int bh = (cls >> 2) & 1, bw = (cls >> 1) & 1, bd = cls & 1;
            int rgn_n = ((bh ? (an < 4 ? 1 : 2) : 0) * 3 + (bw ? (bn < 4 ? 1 : 2) : 0)) * 3
                      + (bd ? (cn < 4 ? 1 : 2) : 0);
            int rgn_m = ((bh ? (am < 4 ? 1 : 2) : 0) * 3 + (bw ? (bm < 4 ? 1 : 2) : 0)) * 3
                      + (bd ? (cm < 4 ? 1 : 2) : 0);
            if (rgn_n != rgn_m) v -= 100.0f * LOG2E;
        }
        g_SB[gid] = v;
    }
}

// ---------------------------------------------------------------------------
// LayerNorm #1 (one warp per token): gather + shift + partition -> bf16
// ---------------------------------------------------------------------------
__global__ void __launch_bounds__(256) ln_kernel(const float* __restrict__ in,
                                                 const float* __restrict__ gamma,
                                                 const float* __restrict__ beta)
{
    int gw   = (blockIdx.x * 256 + threadIdx.x) >> 5;
    int lane = threadIdx.x & 31;
    if (gw >= LTOK) return;

    int w = gw / NTOK, n = gw - w * NTOK;
    int iH = w >> 5, iW = (w >> 2) & 7, iD = w & 3;
    int a = n / 49; int r = n - a * 49; int b = r / 7; int c = r - b * 7;
    int th = iH * 7 + a + 3; if (th >= HH)   th -= HH;
    int tw = iW * 7 + b + 3; if (tw >= WWID) tw -= WWID;
    int td = iD * 7 + c + 3; if (td >= DDEP) td -= DDEP;
    int src = (th * WWID + tw) * DDEP + td;
    if (lane == 0) g_DST[gw] = src;
    const float* inp = in + (size_t)src * CDIM;
    __nv_bfloat16* outp = g_Hb + (size_t)gw * CDIM;

    float v0 = inp[lane], v1 = inp[lane + 32], v2 = inp[lane + 64];
    float s  = v0 + v1 + v2;
    float ss = fmaf(v0, v0, fmaf(v1, v1, v2 * v2));
#pragma unroll
    for (int o = 16; o; o >>= 1) {
        s  += __shfl_xor_sync(0xffffffffu, s, o);
        ss += __shfl_xor_sync(0xffffffffu, ss, o);
    }
    float mean = s * (1.0f / 96.0f);
    float var  = ss * (1.0f / 96.0f) - mean * mean;
    float inv  = rsqrtf(var + 1e-5f);
    outp[lane]      = __float2bfloat16((v0 - mean) * inv * gamma[lane]      + beta[lane]);
    outp[lane + 32] = __float2bfloat16((v1 - mean) * inv * gamma[lane + 32] + beta[lane + 32]);
    outp[lane + 64] = __float2bfloat16((v2 - mean) * inv * gamma[lane + 64] + beta[lane + 64]);
}

// ---------------------------------------------------------------------------
// cp.async bf16 mma GEMM: C[128,96] = A[128,K] @ Wt[96,K]^T
// MODE 0: qkv (q-scale*log2e, direct bf16)  MODE 1: proj (+res +LN2, staged)
// MODE 2: fc1 (GELU, direct bf16)           MODE 3: fc2 (+res -> d_out, staged)
// ---------------------------------------------------------------------------
#define KPAD2 104
#define A_STG (128 * KPAD2 * 2)
#define B_STG (96 * KPAD2 * 2)
#define STAGE_BYTES (A_STG + B_STG)
#define GEMM_SMEM_1 49664
#define GEMM_SMEM_2 (2 * STAGE_BYTES)

template <int MODE>
__global__ void __launch_bounds__(256, 3) gemm_mma(const float* __restrict__ bias,
                                                   const float* __restrict__ res,
                                                   float* __restrict__ outp,
                                                   int Kb,
                                                   const float* __restrict__ g2,
                                                   const float* __restrict__ b2)
{
    extern __shared__ __align__(16) char smraw[];
    float* Sf = (float*)smraw;

    const __nv_bfloat16* A  = (MODE == 0) ? g_Hb : (MODE == 1) ? g_Ob
                            : (MODE == 2) ? g_X2b : g_FFb;
    const __nv_bfloat16* Wt = (MODE == 0) ? g_WtQKVh : (MODE == 1) ? g_WtPROJh
                            : (MODE == 2) ? g_WtFC1h : g_WtFC2h;

    int tid  = threadIdx.x;
    int wid  = tid >> 5, lane = tid & 31;
    int wr   = wid >> 1, wc = wid & 1;
    int g    = lane >> 2, c = lane & 3;
    int m0   = blockIdx.y * BM;
    int n0   = blockIdx.x * BN;

    uint32_t smem_base = (uint32_t)__cvta_generic_to_shared(smraw);

    const __nv_bfloat16* Agm = A  + (size_t)m0 * Kb;
    const __nv_bfloat16* Bgm = Wt + (size_t)n0 * Kb;

    auto stage = [&](int chunk, int buf) {
        uint32_t dstA = smem_base + buf * STAGE_BYTES;
        uint32_t dstB = dstA + A_STG;
        const __nv_bfloat16* As = Agm + chunk * 96;
        const __nv_bfloat16* Bs = Bgm + chunk * 96;
#pragma unroll
        for (int i = 0; i < 6; i++) {
            int idx = tid + (i << 8);
            int row = idx / 12, c16 = idx - row * 12;
            cp16(dstA + (uint32_t)((row * KPAD2 + c16 * 8) * 2),
                 As + (size_t)row * Kb + c16 * 8);
        }
#pragma unroll
        for (int i = 0; i < 5; i++) {
            int idx = tid + (i << 8);
            if (idx < 1152) {
                int row = idx / 12, c16 = idx - row * 12;
                cp16(dstB + (uint32_t)((row * KPAD2 + c16 * 8) * 2),
                     Bs + (size_t)row * Kb + c16 * 8);
            }
        }
        asm volatile("cp.async.commit_group;" ::: "memory");
    };

    int nc = Kb / 96;
    stage(0, 0);
    if (nc > 1) stage(1, 1);
    if (nc > 1) asm volatile("cp.async.wait_group 1;" ::: "memory");
    else        asm volatile("cp.async.wait_group 0;" ::: "memory");
    __syncthreads();

    float acc[2][6][4];
#pragma unroll
    for (int t = 0; t < 2; t++)
#pragma unroll
        for (int u = 0; u < 6; u++)
#pragma unroll
            for (int j = 0; j < 4; j++) acc[t][u][j] = 0.0f;

    int rowoff = lane & 15;
    int koff   = (lane >> 4) << 3;
    uint32_t aAddr0 = smem_base + (uint32_t)(((wr * 32 + rowoff) * KPAD2 + koff) * 2);
    uint32_t bAddr0 = smem_base + A_STG + (uint32_t)(((wc * 48 + rowoff) * KPAD2 + koff) * 2);

    for (int chv = 0; chv < nc; chv++) {
        uint32_t aBuf = aAddr0 + (chv & 1) * STAGE_BYTES;
        uint32_t bBuf = bAddr0 + (chv & 1) * STAGE_BYTES;
#pragma unroll
        for (int ks = 0; ks < 6; ks++) {
            uint32_t a[2][4];
#pragma unroll
            for (int t = 0; t < 2; t++)
                ldsm4(a[t][0], a[t][1], a[t][2], a[t][3],
                      aBuf + (uint32_t)((t * 16 * KPAD2 + ks * 16) * 2));
            uint32_t bq[6][2];
#pragma unroll
            for (int p = 0; p < 3; p++) {
                uint32_t q0, q1, q2, q3;
                ldsm4(q0, q1, q2, q3,
                      bBuf + (uint32_t)((p * 16 * KPAD2 + ks * 16) * 2));
                bq[2 * p][0] = q0; bq[2 * p + 1][0] = q1;
                bq[2 * p][1] = q2; bq[2 * p + 1][1] = q3;
            }
#pragma unroll
            for (int u = 0; u < 6; u++) {
                mma16(acc[0][u], a[0], bq[u][0], bq[u][1]);
                mma16(acc[1][u], a[1], bq[u][0], bq[u][1]);
            }
        }
        if (chv + 1 < nc) {
            __syncthreads();
            if (chv + 2 < nc) stage(chv + 2, chv & 1);
            if (chv + 2 < nc) asm volatile("cp.async.wait_group 1;" ::: "memory");
            else              asm volatile("cp.async.wait_group 0;" ::: "memory");
            __syncthreads();
        }
    }

    if (MODE == 0 || MODE == 2) {
        const int Nout = (MODE == 0) ? 288 : 384;
        __nv_bfloat16* Og = (MODE == 0) ? g_QKVh : g_FFb;
#pragma unroll
        for (int t = 0; t < 2; t++) {
#pragma unroll
            for (int u = 0; u < 6; u++) {
                int r0 = m0 + wr * 32 + t * 16 + g;
                int nn = n0 + wc * 48 + u * 8 + 2 * c;
                float b0 = __ldg(bias + nn);
                float b1 = __ldg(bias + nn + 1);
                float v0 = acc[t][u][0] + b0, v1 = acc[t][u][1] + b1;
                float v2 = acc[t][u][2] + b0, v3 = acc[t][u][3] + b1;
                if (MODE == 0 && n0 == 0) {
                    // 1/sqrt(32) * log2(e): softmax runs in base-2 domain
                    v0 *= 0.25503485943222433f; v1 *= 0.25503485943222433f;
                    v2 *= 0.25503485943222433f; v3 *= 0.25503485943222433f;
                }
                if (MODE == 2) {
                    v0 = 0.5f * v0 * (1.0f + erff(v0 * 0.70710678118654752f));
                    v1 = 0.5f * v1 * (1.0f + erff(v1 * 0.70710678118654752f));
                    v2 = 0.5f * v2 * (1.0f + erff(v2 * 0.70710678118654752f));
                    v3 = 0.5f * v3 * (1.0f + erff(v3 * 0.70710678118654752f));
                }
                *(uint32_t*)(Og + (size_t)r0 * Nout + nn)       = bf2(v0, v1);
                *(uint32_t*)(Og + (size_t)(r0 + 8) * Nout + nn) = bf2(v2, v3);
            }
        }
        return;
    }

    __syncthreads();
#pragma unroll
    for (int t = 0; t < 2; t++) {
#pragma unroll
        for (int u = 0; u < 6; u++) {
            int r0 = wr * 32 + t * 16 + g;
            int nn = wc * 48 + u * 8 + 2 * c;
            float b0 = __ldg(bias + n0 + nn);
            float b1 = __ldg(bias + n0 + nn + 1);
            Sf[r0 * 97 + nn]       = acc[t][u][0] + b0;
            Sf[r0 * 97 + nn + 1]   = acc[t][u][1] + b1;
            Sf[(r0 + 8) * 97 + nn]     = acc[t][u][2] + b0;
            Sf[(r0 + 8) * 97 + nn + 1] = acc[t][u][3] + b1;
        }
    }
    __syncthreads();

#pragma unroll
    for (int i = 0; i < 12; i++) {
        int idx = tid + (i << 8);
        int row = idx / 24, q4 = idx - row * 24;
        int m = m0 + row, n = n0 + (q4 << 2);
        float* sp = Sf + row * 97 + (q4 << 2);
        float4 v; v.x = sp[0]; v.y = sp[1]; v.z = sp[2]; v.w = sp[3];
        if (MODE == 1) {
            int d0 = g_DST[m];
            float4 r = *(const float4*)(res + (size_t)d0 * 96 + n);
            v.x += r.x; v.y += r.y; v.z += r.z; v.w += r.w;
            *(float4*)(g_X + (size_t)d0 * 96 + n) = v;
            sp[0] = v.x; sp[1] = v.y; sp[2] = v.z; sp[3] = v.w;
        } else {
            float4 r = *(const float4*)(g_X + (size_t)m * 96 + n);
            v.x += r.x; v.y += r.y; v.z += r.z; v.w += r.w;
            *(float4*)(outp + (size_t)m * 96 + n) = v;
        }
    }

    if (MODE == 1) {
        __syncthreads();
        int row = tid >> 1, half = tid & 1;
        const float* rp = Sf + row * 97 + half * 48;
        float s = 0.f, ss = 0.f;
#pragma unroll
        for (int j = 0; j < 48; j++) {
            float v = rp[j];
            s += v; ss = fmaf(v, v, ss);
        }
        s  += __shfl_xor_sync(0xffffffffu, s, 1);
        ss += __shfl_xor_sync(0xffffffffu, ss, 1);
        float mean = s * (1.0f / 96.0f);
        float var  = ss * (1.0f / 96.0f) - mean * mean;
        float inv  = rsqrtf(var + 1e-5f);
        int d0 = g_DST[m0 + row];
        __nv_bfloat16* op = g_X2b + (size_t)d0 * 96 + half * 48;
#pragma unroll
        for (int j4 = 0; j4 < 12; j4++) {
            int n = half * 48 + j4 * 4;
            float o0 = (rp[j4 * 4]     - mean) * inv * __ldg(g2 + n)     + __ldg(b2 + n);
            float o1 = (rp[j4 * 4 + 1] - mean) * inv * __ldg(g2 + n + 1) + __ldg(b2 + n + 1);
            float o2 = (rp[j4 * 4 + 2] - mean) * inv * __ldg(g2 + n + 2) + __ldg(b2 + n + 2);
            float o3 = (rp[j4 * 4 + 3] - mean) * inv * __ldg(g2 + n + 3) + __ldg(b2 + n + 3);
            uint2 u; u.x = bf2(o0, o1); u.y = bf2(o2, o3);
            *(uint2*)(op + j4 * 4) = u;
        }
    }
}

// ---------------------------------------------------------------------------
// bf16 MMA attention, fixed-shift exp2 softmax, register-trimmed for
// 2 blocks/SM (22 warps): single K fragment buffer, per-ks V loads,
// 32-bit bias row offsets, non-unrolled key loop.
// ---------------------------------------------------------------------------
#define NPAD 352
#define KP 40
#define ATTN_SMEM (2 * NPAD * KP * 2)        // 56320 B

__global__ void __launch_bounds__(352, 2) attn_mma(const float* __restrict__ rpb)
{
    extern __shared__ __align__(16) char smraw[];
    __nv_bfloat16* Ksp = (__nv_bfloat16*)smraw;
    __nv_bfloat16* Vsp = Ksp + NPAD * KP;

    int w   = blockIdx.x / 3;
    int h   = blockIdx.x - w * 3;
    int tid = threadIdx.x;
    const __nv_bfloat16* base = g_QKVh + (size_t)w * NTOK * 288;

    uint32_t smem_base = (uint32_t)__cvta_generic_to_shared(smraw);
    uint32_t Kbase = smem_base;
    uint32_t Vbase = smem_base + NPAD * KP * 2;

    for (int i = tid; i < NTOK * 4; i += 352) {
        int n = i >> 2, j = (i & 3) << 3;
        const __nv_bfloat16* bp = base + n * 288 + h * 32 + j;
        cp16(Kbase + (uint32_t)((n * KP + j) * 2), bp + 96);
        cp16(Vbase + (uint32_t)((n * KP + j) * 2), bp + 192);
    }
    for (int i = NTOK * 16 + tid; i < NPAD * 16; i += 352) {
        int n = i >> 4, j = (i & 15) << 1;
        *(uint32_t*)(Ksp + n * KP + j) = 0;
        *(uint32_t*)(Vsp + n * KP + j) = 0;
    }
    asm volatile("cp.async.commit_group;" ::: "memory");
    asm volatile("cp.async.wait_group 0;" ::: "memory");
    __syncthreads();

    int wid  = tid >> 5, lane = tid & 31;
    int g    = lane >> 2, c = lane & 3;
    int q0   = wid * 32;

    int iH = w >> 5, iW = (w >> 2) & 7, iD = w & 3;
    int cls = ((iH == 7) << 2) | ((iW == 7) << 1) | (iD == 3);
    const float* SB = g_SB + (size_t)(cls * 3 + h) * NTOK * SBROW;

    int l7  = lane & 7;
    int b3  = (lane >> 3) & 1;
    int b4  = (lane >> 4) & 1;
    uint32_t kAddr = Kbase + (uint32_t)((((b4 << 3) + l7) * KP + (b3 << 3)) * 2);
    uint32_t vAddr = Vbase + (uint32_t)((((b3 << 3) + l7) * KP + (b4 << 3)) * 2);

    uint32_t qa[2][2][4];
    int sbo[4];   // 32-bit row offsets into SB
#pragma unroll
    for (int t = 0; t < 2; t++) {
#pragma unroll
        for (int rr = 0; rr < 2; rr++) {
            int row = q0 + t * 16 + rr * 8 + g;
            int rc  = (row < NTOK) ? row : NTOK - 1;
            sbo[t * 2 + rr] = rc * SBROW;
            const __nv_bfloat16* qp = base + rc * 288 + h * 32;
#pragma unroll
            for (int ks = 0; ks < 2; ks++) {
                qa[t][ks][rr]     = *(const uint32_t*)(qp + ks * 16 + 2 * c);
                qa[t][ks][rr + 2] = *(const uint32_t*)(qp + ks * 16 + 2 * c + 8);
            }
        }
    }

    float lp[4] = {0.f, 0.f, 0.f, 0.f};
    float o[2][4][4];
#pragma unroll
    for (int t = 0; t < 2; t++)
#pragma unroll
        for (int nb = 0; nb < 4; nb++)
#pragma unroll
            for (int j = 0; j < 4; j++) o[t][nb][j] = 0.f;

#pragma unroll 1
    for (int kc = 0; kc < NPAD; kc += 32) {
        // K fragments for this chunk
        uint32_t kf[16];
#pragma unroll
        for (int p = 0; p < 2; p++)
#pragma unroll
            for (int ks = 0; ks < 2; ks++)
                ldsm4(kf[p * 8 + ks * 4 + 0], kf[p * 8 + ks * 4 + 1],
                      kf[p * 8 + ks * 4 + 2], kf[p * 8 + ks * 4 + 3],
                      kAddr + (uint32_t)(((kc + p * 16) * KP + ks * 16) * 2));

        float sa[2][4][4];
#pragma unroll
        for (int t = 0; t < 2; t++)
#pragma unroll
            for (int nb = 0; nb < 4; nb++)
#pragma unroll
                for (int j = 0; j < 4; j++) sa[t][nb][j] = 0.f;

#pragma unroll
        for (int p = 0; p < 2; p++) {
#pragma unroll
            for (int ks = 0; ks < 2; ks++) {
                const uint32_t* kb = kf + p * 8 + ks * 4;
                mma16(sa[0][2 * p],     qa[0][ks], kb[0], kb[1]);
                mma16(sa[1][2 * p],     qa[1][ks], kb[0], kb[1]);
                mma16(sa[0][2 * p + 1], qa[0][ks], kb[2], kb[3]);
                mma16(sa[1][2 * p + 1], qa[1][ks], kb[2], kb[3]);
            }
        }

        // bias + fixed-shift exp2; accumulate partial l
#pragma unroll
        for (int t = 0; t < 2; t++) {
#pragma unroll
            for (int nb = 0; nb < 4; nb++) {
                int coff = kc + nb * 8 + 2 * c;
                float2 bv0 = *(const float2*)(SB + sbo[t * 2]     + coff);
                float2 bv1 = *(const float2*)(SB + sbo[t * 2 + 1] + coff);
                float p0 = ex2(sa[t][nb][0] + bv0.x - SMAX);
                float p1 = ex2(sa[t][nb][1] + bv0.y - SMAX);
                float p2 = ex2(sa[t][nb][2] + bv1.x - SMAX);
                float p3 = ex2(sa[t][nb][3] + bv1.y - SMAX);
                sa[t][nb][0] = p0; sa[t][nb][1] = p1;
                sa[t][nb][2] = p2; sa[t][nb][3] = p3;
                lp[t * 2]     += p0 + p1;
                lp[t * 2 + 1] += p2 + p3;
            }
        }

        // O += P V, per k16 step (V fragments live 8 at a time)
#pragma unroll
        for (int ks = 0; ks < 2; ks++) {
            uint32_t pa[2][4];
#pragma unroll
            for (int t = 0; t < 2; t++) {
                pa[t][0] = bf2(sa[t][2 * ks][0],     sa[t][2 * ks][1]);
                pa[t][1] = bf2(sa[t][2 * ks][2],     sa[t][2 * ks][3]);
                pa[t][2] = bf2(sa[t][2 * ks + 1][0], sa[t][2 * ks + 1][1]);
                pa[t][3] = bf2(sa[t][2 * ks + 1][2], sa[t][2 * ks + 1][3]);
            }
#pragma unroll
            for (int db = 0; db < 2; db++) {
                uint32_t v0, v1, v2, v3;
                ldsm4t(v0, v1, v2, v3,
                       vAddr + (uint32_t)(((kc + ks * 16) * KP + db * 16) * 2));
                mma16(o[0][2 * db],     pa[0], v0, v1);
                mma16(o[1][2 * db],     pa[1], v0, v1);
                mma16(o[0][2 * db + 1], pa[0], v2, v3);
                mma16(o[1][2 * db + 1], pa[1], v2, v3);
            }
        }
    }

    // deferred l reduction
    float inv[4];
#pragma unroll
    for (int ri = 0; ri < 4; ri++) {
        float l = lp[ri];
        l += __shfl_xor_sync(0xffffffffu, l, 1);
        l += __shfl_xor_sync(0xffffffffu, l, 2);
        inv[ri] = 1.0f / l;
    }

#pragma unroll
    for (int t = 0; t < 2; t++) {
        int r0 = q0 + t * 16 + g;
#pragma unroll
        for (int rr = 0; rr < 2; rr++) {
            int row = r0 + rr * 8;
            if (row < NTOK) {
                int ri = t * 2 + rr;
                __nv_bfloat16* op = g_Ob + ((size_t)w * NTOK + row) * CDIM + h * 32;
#pragma unroll
                for (int nb = 0; nb < 4; nb++) {
                    uint32_t p = bf2(o[t][nb][rr * 2] * inv[ri],
                                     o[t][nb][rr * 2 + 1] * inv[ri]);
                    *(uint32_t*)(op + nb * 8 + 2 * c) = p;
                }
            }
        }
    }
}

// ---------------------------------------------------------------------------
// Launch
// ---------------------------------------------------------------------------
extern "C" void kernel_launch(void* const* d_in, const int* in_sizes, int n_in,
                              void* d_out, int out_size)
{
    const float* x      = (const float*)d_in[0];
    const float* n1g    = (const float*)d_in[1];
    const float* n1b    = (const float*)d_in[2];
    const float* qkv_w  = (const float*)d_in[3];
    const float* qkv_b  = (const float*)d_in[4];
    const float* rpb    = (const float*)d_in[5];
    const float* proj_w = (const float*)d_in[6];
    const float* proj_b = (const float*)d_in[7];
    const float* n2g    = (const float*)d_in[8];
    const float* n2b    = (const float*)d_in[9];
    const float* fc1_w  = (const float*)d_in[10];
    const float* fc1_b  = (const float*)d_in[11];
    const float* fc2_w  = (const float*)d_in[12];
    const float* fc2_b  = (const float*)d_in[13];
    float* out = (float*)d_out;

    cudaFuncSetAttribute(gemm_mma<0>, cudaFuncAttributeMaxDynamicSharedMemorySize, GEMM_SMEM_1);
    cudaFuncSetAttribute(gemm_mma<1>, cudaFuncAttributeMaxDynamicSharedMemorySize, GEMM_SMEM_1);
    cudaFuncSetAttribute(gemm_mma<2>, cudaFuncAttributeMaxDynamicSharedMemorySize, GEMM_SMEM_1);
    cudaFuncSetAttribute(gemm_mma<3>, cudaFuncAttributeMaxDynamicSharedMemorySize, GEMM_SMEM_2);
    cudaFuncSetAttribute(attn_mma, cudaFuncAttributeMaxDynamicSharedMemorySize, ATTN_SMEM);

    prep_kernel<<<(24 * NTOK * SBROW + 255) / 256, 256>>>(qkv_w, proj_w, fc1_w, fc2_w, rpb);

    ln_kernel<<<LTOK / 8, 256>>>(x, n1g, n1b);

    gemm_mma<0><<<dim3(3, 686), 256, GEMM_SMEM_1>>>(qkv_b, nullptr, nullptr, 96, nullptr, nullptr);

    attn_mma<<<NWIN * NHEAD, 352, ATTN_SMEM>>>(rpb);

    gemm_mma<1><<<dim3(1, 686), 256, GEMM_SMEM_1>>>(proj_b, x, nullptr, 96, n2g, n2b);

    gemm_mma<2><<<dim3(4, 686), 256, GEMM_SMEM_1>>>(fc1_b, nullptr, nullptr, 96, nullptr, nullptr);

    gemm_mma<3><<<dim3(1, 686), 256, GEMM_SMEM_2>>>(fc2_b, nullptr, out, 384, nullptr, nullptr);
}

// round 17
// speedup vs baseline: 1.2478x; 1.2478x over previous
#include <cuda_runtime.h>
#include <cuda_bf16.h>
#include <cstdint>

// ---------------------------------------------------------------------------
// Problem constants
// ---------------------------------------------------------------------------
#define HH   56
#define WWID 56
#define DDEP 28
#define LTOK 87808          // 56*56*28
#define CDIM 96
#define NWIN 256
#define NTOK 343
#define NHEAD 3
#define FF   384
#define BN   96             // GEMM N tile
#define BM   128            // GEMM M tile
#define LOG2E 1.4426950408889634f
#define SMAX 16.0f          // fixed softmax shift (log2 domain)

// ---------------------------------------------------------------------------
// Scratch (device globals; no allocation allowed)
// ---------------------------------------------------------------------------
__device__ __align__(16) float g_X  [(size_t)LTOK * CDIM];
__device__ int g_DST[LTOK];
// bf16 activations
__device__ __align__(16) __nv_bfloat16 g_QKVh[(size_t)LTOK * 288];
__device__ __align__(16) __nv_bfloat16 g_Hb [(size_t)LTOK * CDIM];
__device__ __align__(16) __nv_bfloat16 g_Ob [(size_t)LTOK * CDIM];
__device__ __align__(16) __nv_bfloat16 g_X2b[(size_t)LTOK * CDIM];
__device__ __align__(16) __nv_bfloat16 g_FFb[(size_t)LTOK * FF];
// bf16 pre-transposed weights [N,K]
__device__ __align__(16) __nv_bfloat16 g_WtQKVh [288 * 96];
__device__ __align__(16) __nv_bfloat16 g_WtPROJh[96 * 96];
__device__ __align__(16) __nv_bfloat16 g_WtFC1h [384 * 96];
__device__ __align__(16) __nv_bfloat16 g_WtFC2h [96 * 384];
// precomputed bias+mask table (log2-domain): [8 classes][3 heads][343][352]
#define SBROW 352
__device__ __align__(16) float g_SB[24 * NTOK * SBROW];

// ---------------------------------------------------------------------------
// helpers
// ---------------------------------------------------------------------------
__device__ __forceinline__ void mma16(float* c, const uint32_t* a, uint32_t b0, uint32_t b1) {
    asm("mma.sync.aligned.m16n8k16.row.col.f32.bf16.bf16.f32 "
        "{%0,%1,%2,%3}, {%4,%5,%6,%7}, {%8,%9}, {%0,%1,%2,%3};"
        : "+f"(c[0]), "+f"(c[1]), "+f"(c[2]), "+f"(c[3])
        : "r"(a[0]), "r"(a[1]), "r"(a[2]), "r"(a[3]), "r"(b0), "r"(b1));
}
__device__ __forceinline__ void ldsm4(uint32_t& r0, uint32_t& r1, uint32_t& r2, uint32_t& r3,
                                      uint32_t addr) {
    asm volatile("ldmatrix.sync.aligned.m8n8.x4.shared.b16 {%0,%1,%2,%3}, [%4];"
        : "=r"(r0), "=r"(r1), "=r"(r2), "=r"(r3) : "r"(addr));
}
__device__ __forceinline__ void ldsm4t(uint32_t& r0, uint32_t& r1, uint32_t& r2, uint32_t& r3,
                                       uint32_t addr) {
    asm volatile("ldmatrix.sync.aligned.m8n8.x4.trans.shared.b16 {%0,%1,%2,%3}, [%4];"
        : "=r"(r0), "=r"(r1), "=r"(r2), "=r"(r3) : "r"(addr));
}
__device__ __forceinline__ uint32_t bf2(float lo, float hi) {
    uint32_t d;
    asm("cvt.rn.bf16x2.f32 %0, %1, %2;" : "=r"(d) : "f"(hi), "f"(lo));
    return d;
}
__device__ __forceinline__ void cp16(uint32_t dst, const void* src) {
    asm volatile("cp.async.cg.shared.global [%0], [%1], 16;" :: "r"(dst), "l"(src));
}
__device__ __forceinline__ float ex2(float x) {
    float y;
    asm("ex2.approx.f32 %0, %1;" : "=f"(y) : "f"(x));
    return y;
}

// ---------------------------------------------------------------------------
// Prep: weight transposes + bias+mask table (log2 domain), one launch
// ---------------------------------------------------------------------------
__global__ void prep_kernel(const float* __restrict__ qkv_w,
                            const float* __restrict__ proj_w,
                            const float* __restrict__ fc1_w,
                            const float* __restrict__ fc2_w,
                            const float* __restrict__ rpb)
{
    int gid = blockIdx.x * 256 + threadIdx.x;

    if (gid < 110592) {
        int idx = gid;
        if (idx < 27648) {
            int k = idx / 288, n = idx - k * 288;
            g_WtQKVh[n * 96 + k] = __float2bfloat16(qkv_w[idx]);
        } else if (idx < 36864) {
            int j = idx - 27648;
            int k = j / 96, n = j - k * 96;
            g_WtPROJh[n * 96 + k] = __float2bfloat16(proj_w[j]);
        } else if (idx < 73728) {
            int j = idx - 36864;
            int k = j / 384, n = j - k * 384;
            g_WtFC1h[n * 96 + k] = __float2bfloat16(fc1_w[j]);
        } else {
            int j = idx - 73728;
            int k = j / 96, n = j - k * 96;
            g_WtFC2h[n * 384 + k] = __float2bfloat16(fc2_w[j]);
        }
    }

    if (gid < 24 * NTOK * SBROW) {
        int m  = gid % SBROW;
        int t  = gid / SBROW;
        int n  = t % NTOK;
        int ch = t / NTOK;
        int h  = ch % 3, cls = ch / 3;
        float v;
        if (m >= NTOK) {
            v = -30000.0f;
        } else {
            int an = n / 49, rn = n - an * 49, bn = rn / 7, cn = rn - bn * 7;
            int am = m / 49, rm = m - am * 49, bm = rm / 7, cm = rm - bm * 7;
            int sub_n = an * 169 + bn * 13 + cn;
            int sub_m = am * 169 + bm * 13 + cm;
            v = rpb[(1098 + sub_n - sub_m) * 3 + h] * LOG2E;
            int bh = (cls >> 2) & 1, bw = (cls >> 1) & 1, bd = cls & 1;
            int rgn_n = ((bh ? (an < 4 ? 1 : 2) : 0) * 3 + (bw ? (bn < 4 ? 1 : 2) : 0)) * 3
                      + (bd ? (cn < 4 ? 1 : 2) : 0);
            int rgn_m = ((bh ? (am < 4 ? 1 : 2) : 0) * 3 + (bw ? (bm < 4 ? 1 : 2) : 0)) * 3
                      + (bd ? (cm < 4 ? 1 : 2) : 0);
            if (rgn_n != rgn_m) v -= 100.0f * LOG2E;
        }
        g_SB[gid] = v;
    }
}

// ---------------------------------------------------------------------------
// LayerNorm #1 (one warp per token): gather + shift + partition -> bf16
// ---------------------------------------------------------------------------
__global__ void __launch_bounds__(256) ln_kernel(const float* __restrict__ in,
                                                 const float* __restrict__ gamma,
                                                 const float* __restrict__ beta)
{
    int gw   = (blockIdx.x * 256 + threadIdx.x) >> 5;
    int lane = threadIdx.x & 31;
    if (gw >= LTOK) return;

    int w = gw / NTOK, n = gw - w * NTOK;
    int iH = w >> 5, iW = (w >> 2) & 7, iD = w & 3;
    int a = n / 49; int r = n - a * 49; int b = r / 7; int c = r - b * 7;
    int th = iH * 7 + a + 3; if (th >= HH)   th -= HH;
    int tw = iW * 7 + b + 3; if (tw >= WWID) tw -= WWID;
    int td = iD * 7 + c + 3; if (td >= DDEP) td -= DDEP;
    int src = (th * WWID + tw) * DDEP + td;
    if (lane == 0) g_DST[gw] = src;
    const float* inp = in + (size_t)src * CDIM;
    __nv_bfloat16* outp = g_Hb + (size_t)gw * CDIM;

    float v0 = inp[lane], v1 = inp[lane + 32], v2 = inp[lane + 64];
    float s  = v0 + v1 + v2;
    float ss = fmaf(v0, v0, fmaf(v1, v1, v2 * v2));
#pragma unroll
    for (int o = 16; o; o >>= 1) {
        s  += __shfl_xor_sync(0xffffffffu, s, o);
        ss += __shfl_xor_sync(0xffffffffu, ss, o);
    }
    float mean = s * (1.0f / 96.0f);
    float var  = ss * (1.0f / 96.0f) - mean * mean;
    float inv  = rsqrtf(var + 1e-5f);
    outp[lane]      = __float2bfloat16((v0 - mean) * inv * gamma[lane]      + beta[lane]);
    outp[lane + 32] = __float2bfloat16((v1 - mean) * inv * gamma[lane + 32] + beta[lane + 32]);
    outp[lane + 64] = __float2bfloat16((v2 - mean) * inv * gamma[lane + 64] + beta[lane + 64]);
}

// ---------------------------------------------------------------------------
// cp.async bf16 mma GEMM: C[128,96] = A[128,K] @ Wt[96,K]^T
// MODE 0: qkv (q-scale*log2e, direct bf16)  MODE 1: proj (+res +LN2, staged)
// MODE 2: fc1 (GELU, direct bf16)           MODE 3: fc2 (+res -> d_out, staged)
// ---------------------------------------------------------------------------
#define KPAD2 104
#define A_STG (128 * KPAD2 * 2)
#define B_STG (96 * KPAD2 * 2)
#define STAGE_BYTES (A_STG + B_STG)
#define GEMM_SMEM_1 49664
#define GEMM_SMEM_2 (2 * STAGE_BYTES)

template <int MODE>
__global__ void __launch_bounds__(256, 3) gemm_mma(const float* __restrict__ bias,
                                                   const float* __restrict__ res,
                                                   float* __restrict__ outp,
                                                   int Kb,
                                                   const float* __restrict__ g2,
                                                   const float* __restrict__ b2)
{
    extern __shared__ __align__(16) char smraw[];
    float* Sf = (float*)smraw;

    const __nv_bfloat16* A  = (MODE == 0) ? g_Hb : (MODE == 1) ? g_Ob
                            : (MODE == 2) ? g_X2b : g_FFb;
    const __nv_bfloat16* Wt = (MODE == 0) ? g_WtQKVh : (MODE == 1) ? g_WtPROJh
                            : (MODE == 2) ? g_WtFC1h : g_WtFC2h;

    int tid  = threadIdx.x;
    int wid  = tid >> 5, lane = tid & 31;
    int wr   = wid >> 1, wc = wid & 1;
    int g    = lane >> 2, c = lane & 3;
    int m0   = blockIdx.y * BM;
    int n0   = blockIdx.x * BN;

    uint32_t smem_base = (uint32_t)__cvta_generic_to_shared(smraw);

    const __nv_bfloat16* Agm = A  + (size_t)m0 * Kb;
    const __nv_bfloat16* Bgm = Wt + (size_t)n0 * Kb;

    auto stage = [&](int chunk, int buf) {
        uint32_t dstA = smem_base + buf * STAGE_BYTES;
        uint32_t dstB = dstA + A_STG;
        const __nv_bfloat16* As = Agm + chunk * 96;
        const __nv_bfloat16* Bs = Bgm + chunk * 96;
#pragma unroll
        for (int i = 0; i < 6; i++) {
            int idx = tid + (i << 8);
            int row = idx / 12, c16 = idx - row * 12;
            cp16(dstA + (uint32_t)((row * KPAD2 + c16 * 8) * 2),
                 As + (size_t)row * Kb + c16 * 8);
        }
#pragma unroll
        for (int i = 0; i < 5; i++) {
            int idx = tid + (i << 8);
            if (idx < 1152) {
                int row = idx / 12, c16 = idx - row * 12;
                cp16(dstB + (uint32_t)((row * KPAD2 + c16 * 8) * 2),
                     Bs + (size_t)row * Kb + c16 * 8);
            }
        }
        asm volatile("cp.async.commit_group;" ::: "memory");
    };

    int nc = Kb / 96;
    stage(0, 0);
    if (nc > 1) stage(1, 1);
    if (nc > 1) asm volatile("cp.async.wait_group 1;" ::: "memory");
    else        asm volatile("cp.async.wait_group 0;" ::: "memory");
    __syncthreads();

    float acc[2][6][4];
#pragma unroll
    for (int t = 0; t < 2; t++)
#pragma unroll
        for (int u = 0; u < 6; u++)
#pragma unroll
            for (int j = 0; j < 4; j++) acc[t][u][j] = 0.0f;

    int rowoff = lane & 15;
    int koff   = (lane >> 4) << 3;
    uint32_t aAddr0 = smem_base + (uint32_t)(((wr * 32 + rowoff) * KPAD2 + koff) * 2);
    uint32_t bAddr0 = smem_base + A_STG + (uint32_t)(((wc * 48 + rowoff) * KPAD2 + koff) * 2);

    for (int chv = 0; chv < nc; chv++) {
        uint32_t aBuf = aAddr0 + (chv & 1) * STAGE_BYTES;
        uint32_t bBuf = bAddr0 + (chv & 1) * STAGE_BYTES;
#pragma unroll
        for (int ks = 0; ks < 6; ks++) {
            uint32_t a[2][4];
#pragma unroll
            for (int t = 0; t < 2; t++)
                ldsm4(a[t][0], a[t][1], a[t][2], a[t][3],
                      aBuf + (uint32_t)((t * 16 * KPAD2 + ks * 16) * 2));
            uint32_t bq[6][2];
#pragma unroll
            for (int p = 0; p < 3; p++) {
                uint32_t q0, q1, q2, q3;
                ldsm4(q0, q1, q2, q3,
                      bBuf + (uint32_t)((p * 16 * KPAD2 + ks * 16) * 2));
                bq[2 * p][0] = q0; bq[2 * p + 1][0] = q1;
                bq[2 * p][1] = q2; bq[2 * p + 1][1] = q3;
            }
#pragma unroll
            for (int u = 0; u < 6; u++) {
                mma16(acc[0][u], a[0], bq[u][0], bq[u][1]);
                mma16(acc[1][u], a[1], bq[u][0], bq[u][1]);
            }
        }
        if (chv + 1 < nc) {
            __syncthreads();
            if (chv + 2 < nc) stage(chv + 2, chv & 1);
            if (chv + 2 < nc) asm volatile("cp.async.wait_group 1;" ::: "memory");
            else              asm volatile("cp.async.wait_group 0;" ::: "memory");
            __syncthreads();
        }
    }

    if (MODE == 0 || MODE == 2) {
        const int Nout = (MODE == 0) ? 288 : 384;
        __nv_bfloat16* Og = (MODE == 0) ? g_QKVh : g_FFb;
#pragma unroll
        for (int t = 0; t < 2; t++) {
#pragma unroll
            for (int u = 0; u < 6; u++) {
                int r0 = m0 + wr * 32 + t * 16 + g;
                int nn = n0 + wc * 48 + u * 8 + 2 * c;
                float b0 = __ldg(bias + nn);
                float b1 = __ldg(bias + nn + 1);
                float v0 = acc[t][u][0] + b0, v1 = acc[t][u][1] + b1;
                float v2 = acc[t][u][2] + b0, v3 = acc[t][u][3] + b1;
                if (MODE == 0 && n0 == 0) {
                    // 1/sqrt(32) * log2(e): softmax runs in base-2 domain
                    v0 *= 0.25503485943222433f; v1 *= 0.25503485943222433f;
                    v2 *= 0.25503485943222433f; v3 *= 0.25503485943222433f;
                }
                if (MODE == 2) {
                    v0 = 0.5f * v0 * (1.0f + erff(v0 * 0.70710678118654752f));
                    v1 = 0.5f * v1 * (1.0f + erff(v1 * 0.70710678118654752f));
                    v2 = 0.5f * v2 * (1.0f + erff(v2 * 0.70710678118654752f));
                    v3 = 0.5f * v3 * (1.0f + erff(v3 * 0.70710678118654752f));
                }
                *(uint32_t*)(Og + (size_t)r0 * Nout + nn)       = bf2(v0, v1);
                *(uint32_t*)(Og + (size_t)(r0 + 8) * Nout + nn) = bf2(v2, v3);
            }
        }
        return;
    }

    __syncthreads();
#pragma unroll
    for (int t = 0; t < 2; t++) {
#pragma unroll
        for (int u = 0; u < 6; u++) {
            int r0 = wr * 32 + t * 16 + g;
            int nn = wc * 48 + u * 8 + 2 * c;
            float b0 = __ldg(bias + n0 + nn);
            float b1 = __ldg(bias + n0 + nn + 1);
            Sf[r0 * 97 + nn]       = acc[t][u][0] + b0;
            Sf[r0 * 97 + nn + 1]   = acc[t][u][1] + b1;
            Sf[(r0 + 8) * 97 + nn]     = acc[t][u][2] + b0;
            Sf[(r0 + 8) * 97 + nn + 1] = acc[t][u][3] + b1;
        }
    }
    __syncthreads();

#pragma unroll
    for (int i = 0; i < 12; i++) {
        int idx = tid + (i << 8);
        int row = idx / 24, q4 = idx - row * 24;
        int m = m0 + row, n = n0 + (q4 << 2);
        float* sp = Sf + row * 97 + (q4 << 2);
        float4 v; v.x = sp[0]; v.y = sp[1]; v.z = sp[2]; v.w = sp[3];
        if (MODE == 1) {
            int d0 = g_DST[m];
            float4 r = *(const float4*)(res + (size_t)d0 * 96 + n);
            v.x += r.x; v.y += r.y; v.z += r.z; v.w += r.w;
            *(float4*)(g_X + (size_t)d0 * 96 + n) = v;
            sp[0] = v.x; sp[1] = v.y; sp[2] = v.z; sp[3] = v.w;
        } else {
            float4 r = *(const float4*)(g_X + (size_t)m * 96 + n);
            v.x += r.x; v.y += r.y; v.z += r.z; v.w += r.w;
            *(float4*)(outp + (size_t)m * 96 + n) = v;
        }
    }

    if (MODE == 1) {
        __syncthreads();
        int row = tid >> 1, half = tid & 1;
        const float* rp = Sf + row * 97 + half * 48;
        float s = 0.f, ss = 0.f;
#pragma unroll
        for (int j = 0; j < 48; j++) {
            float v = rp[j];
            s += v; ss = fmaf(v, v, ss);
        }
        s  += __shfl_xor_sync(0xffffffffu, s, 1);
        ss += __shfl_xor_sync(0xffffffffu, ss, 1);
        float mean = s * (1.0f / 96.0f);
        float var  = ss * (1.0f / 96.0f) - mean * mean;
        float inv  = rsqrtf(var + 1e-5f);
        int d0 = g_DST[m0 + row];
        __nv_bfloat16* op = g_X2b + (size_t)d0 * 96 + half * 48;
#pragma unroll
        for (int j4 = 0; j4 < 12; j4++) {
            int n = half * 48 + j4 * 4;
            float o0 = (rp[j4 * 4]     - mean) * inv * __ldg(g2 + n)     + __ldg(b2 + n);
            float o1 = (rp[j4 * 4 + 1] - mean) * inv * __ldg(g2 + n + 1) + __ldg(b2 + n + 1);
            float o2 = (rp[j4 * 4 + 2] - mean) * inv * __ldg(g2 + n + 2) + __ldg(b2 + n + 2);
            float o3 = (rp[j4 * 4 + 3] - mean) * inv * __ldg(g2 + n + 3) + __ldg(b2 + n + 3);
            uint2 u; u.x = bf2(o0, o1); u.y = bf2(o2, o3);
            *(uint2*)(op + j4 * 4) = u;
        }
    }
}

// ---------------------------------------------------------------------------
// bf16 MMA attention (R15 structure, 1 block/SM): fixed-shift exp2 softmax,
// K frags double-buffered, V frags preloaded, bias LDGs hoisted to the top
// of each chunk so their L2 latency overlaps mma/ldsm work.
// ---------------------------------------------------------------------------
#define NPAD 352
#define KP 40
#define ATTN_SMEM (2 * NPAD * KP * 2)        // 56320 B

__global__ void __launch_bounds__(352, 1) attn_mma(const float* __restrict__ rpb)
{
    extern __shared__ __align__(16) char smraw[];
    __nv_bfloat16* Ksp = (__nv_bfloat16*)smraw;
    __nv_bfloat16* Vsp = Ksp + NPAD * KP;

    int w   = blockIdx.x / 3;
    int h   = blockIdx.x - w * 3;
    int tid = threadIdx.x;
    const __nv_bfloat16* base = g_QKVh + (size_t)w * NTOK * 288;

    uint32_t smem_base = (uint32_t)__cvta_generic_to_shared(smraw);
    uint32_t Kbase = smem_base;
    uint32_t Vbase = smem_base + NPAD * KP * 2;

    for (int i = tid; i < NTOK * 4; i += 352) {
        int n = i >> 2, j = (i & 3) << 3;
        const __nv_bfloat16* bp = base + n * 288 + h * 32 + j;
        cp16(Kbase + (uint32_t)((n * KP + j) * 2), bp + 96);
        cp16(Vbase + (uint32_t)((n * KP + j) * 2), bp + 192);
    }
    for (int i = NTOK * 16 + tid; i < NPAD * 16; i += 352) {
        int n = i >> 4, j = (i & 15) << 1;
        *(uint32_t*)(Ksp + n * KP + j) = 0;
        *(uint32_t*)(Vsp + n * KP + j) = 0;
    }
    asm volatile("cp.async.commit_group;" ::: "memory");
    asm volatile("cp.async.wait_group 0;" ::: "memory");
    __syncthreads();

    int wid  = tid >> 5, lane = tid & 31;
    int g    = lane >> 2, c = lane & 3;
    int q0   = wid * 32;

    int iH = w >> 5, iW = (w >> 2) & 7, iD = w & 3;
    int cls = ((iH == 7) << 2) | ((iW == 7) << 1) | (iD == 3);
    const float* SB = g_SB + (size_t)(cls * 3 + h) * NTOK * SBROW;

    int l7  = lane & 7;
    int b3  = (lane >> 3) & 1;
    int b4  = (lane >> 4) & 1;
    uint32_t kAddr = Kbase + (uint32_t)((((b4 << 3) + l7) * KP + (b3 << 3)) * 2);
    uint32_t vAddr = Vbase + (uint32_t)((((b3 << 3) + l7) * KP + (b4 << 3)) * 2);

    uint32_t qa[2][2][4];
    const float* sbp[4];
#pragma unroll
    for (int t = 0; t < 2; t++) {
#pragma unroll
        for (int rr = 0; rr < 2; rr++) {
            int row = q0 + t * 16 + rr * 8 + g;
            int rc  = (row < NTOK) ? row : NTOK - 1;
            sbp[t * 2 + rr] = SB + (size_t)rc * SBROW;
            const __nv_bfloat16* qp = base + rc * 288 + h * 32;
#pragma unroll
            for (int ks = 0; ks < 2; ks++) {
                qa[t][ks][rr]     = *(const uint32_t*)(qp + ks * 16 + 2 * c);
                qa[t][ks][rr + 2] = *(const uint32_t*)(qp + ks * 16 + 2 * c + 8);
            }
        }
    }

    float lp[4] = {0.f, 0.f, 0.f, 0.f};
    float o[2][4][4];
#pragma unroll
    for (int t = 0; t < 2; t++)
#pragma unroll
        for (int nb = 0; nb < 4; nb++)
#pragma unroll
            for (int j = 0; j < 4; j++) o[t][nb][j] = 0.f;

    uint32_t kfA[16], kfB[16];

    auto loadK = [&](int kc, uint32_t* kf) {
#pragma unroll
        for (int p = 0; p < 2; p++)
#pragma unroll
            for (int ks = 0; ks < 2; ks++)
                ldsm4(kf[p * 8 + ks * 4 + 0], kf[p * 8 + ks * 4 + 1],
                      kf[p * 8 + ks * 4 + 2], kf[p * 8 + ks * 4 + 3],
                      kAddr + (uint32_t)(((kc + p * 16) * KP + ks * 16) * 2));
    };

    auto chunk = [&](int kc, uint32_t* kf, uint32_t* kfn, bool pf) {
        // Hoisted bias loads: issue the L2 LDGs first so their latency
        // overlaps the mma/ldsm sequence below.
        float2 bv[2][4][2];
#pragma unroll
        for (int t = 0; t < 2; t++) {
#pragma unroll
            for (int nb = 0; nb < 4; nb++) {
                int coff = kc + nb * 8 + 2 * c;
                bv[t][nb][0] = *(const float2*)(sbp[t * 2]     + coff);
                bv[t][nb][1] = *(const float2*)(sbp[t * 2 + 1] + coff);
            }
        }

        float sa[2][4][4];
#pragma unroll
        for (int t = 0; t < 2; t++)
#pragma unroll
            for (int nb = 0; nb < 4; nb++)
#pragma unroll
                for (int j = 0; j < 4; j++) sa[t][nb][j] = 0.f;

#pragma unroll
        for (int p = 0; p < 2; p++) {
#pragma unroll
            for (int ks = 0; ks < 2; ks++) {
                const uint32_t* kb = kf + p * 8 + ks * 4;
                mma16(sa[0][2 * p],     qa[0][ks], kb[0], kb[1]);
                mma16(sa[1][2 * p],     qa[1][ks], kb[0], kb[1]);
                mma16(sa[0][2 * p + 1], qa[0][ks], kb[2], kb[3]);
                mma16(sa[1][2 * p + 1], qa[1][ks], kb[2], kb[3]);
            }
        }

        if (pf) loadK(kc + 32, kfn);

        uint32_t vf[16];
#pragma unroll
        for (int ks = 0; ks < 2; ks++)
#pragma unroll
            for (int db = 0; db < 2; db++)
                ldsm4t(vf[ks * 8 + db * 4 + 0], vf[ks * 8 + db * 4 + 1],
                       vf[ks * 8 + db * 4 + 2], vf[ks * 8 + db * 4 + 3],
                       vAddr + (uint32_t)(((kc + ks * 16) * KP + db * 16) * 2));

        // bias + fixed-shift exp2; accumulate partial l
#pragma unroll
        for (int t = 0; t < 2; t++) {
#pragma unroll
            for (int nb = 0; nb < 4; nb++) {
                float p0 = ex2(sa[t][nb][0] + bv[t][nb][0].x - SMAX);
                float p1 = ex2(sa[t][nb][1] + bv[t][nb][0].y - SMAX);
                float p2 = ex2(sa[t][nb][2] + bv[t][nb][1].x - SMAX);
                float p3 = ex2(sa[t][nb][3] + bv[t][nb][1].y - SMAX);
                sa[t][nb][0] = p0; sa[t][nb][1] = p1;
                sa[t][nb][2] = p2; sa[t][nb][3] = p3;
                lp[t * 2]     += p0 + p1;
                lp[t * 2 + 1] += p2 + p3;
            }
        }

#pragma unroll
        for (int ks = 0; ks < 2; ks++) {
            uint32_t pa[2][4];
#pragma unroll
            for (int t = 0; t < 2; t++) {
                pa[t][0] = bf2(sa[t][2 * ks][0],     sa[t][2 * ks][1]);
                pa[t][1] = bf2(sa[t][2 * ks][2],     sa[t][2 * ks][3]);
                pa[t][2] = bf2(sa[t][2 * ks + 1][0], sa[t][2 * ks + 1][1]);
                pa[t][3] = bf2(sa[t][2 * ks + 1][2], sa[t][2 * ks + 1][3]);
            }
#pragma unroll
            for (int db = 0; db < 2; db++) {
                const uint32_t* vb = vf + ks * 8 + db * 4;
                mma16(o[0][2 * db],     pa[0], vb[0], vb[1]);
                mma16(o[1][2 * db],     pa[1], vb[0], vb[1]);
                mma16(o[0][2 * db + 1], pa[0], vb[2], vb[3]);
                mma16(o[1][2 * db + 1], pa[1], vb[2], vb[3]);
            }
        }
    };

    loadK(0, kfA);
    for (int kc = 0; kc < 320; kc += 64) {
        chunk(kc,      kfA, kfB, true);
        chunk(kc + 32, kfB, kfA, true);
    }
    chunk(320, kfA, kfB, false);

    // deferred l reduction
    float inv[4];
#pragma unroll
    for (int ri = 0; ri < 4; ri++) {
        float l = lp[ri];
        l += __shfl_xor_sync(0xffffffffu, l, 1);
        l += __shfl_xor_sync(0xffffffffu, l, 2);
        inv[ri] = 1.0f / l;
    }

#pragma unroll
    for (int t = 0; t < 2; t++) {
        int r0 = q0 + t * 16 + g;
#pragma unroll
        for (int rr = 0; rr < 2; rr++) {
            int row = r0 + rr * 8;
            if (row < NTOK) {
                int ri = t * 2 + rr;
                __nv_bfloat16* op = g_Ob + ((size_t)w * NTOK + row) * CDIM + h * 32;
#pragma unroll
                for (int nb = 0; nb < 4; nb++) {
                    uint32_t p = bf2(o[t][nb][rr * 2] * inv[ri],
                                     o[t][nb][rr * 2 + 1] * inv[ri]);
                    *(uint32_t*)(op + nb * 8 + 2 * c) = p;
                }
            }
        }
    }
}

// ---------------------------------------------------------------------------
// Launch
// ---------------------------------------------------------------------------
extern "C" void kernel_launch(void* const* d_in, const int* in_sizes, int n_in,
                              void* d_out, int out_size)
{
    const float* x      = (const float*)d_in[0];
    const float* n1g    = (const float*)d_in[1];
    const float* n1b    = (const float*)d_in[2];
    const float* qkv_w  = (const float*)d_in[3];
    const float* qkv_b  = (const float*)d_in[4];
    const float* rpb    = (const float*)d_in[5];
    const float* proj_w = (const float*)d_in[6];
    const float* proj_b = (const float*)d_in[7];
    const float* n2g    = (const float*)d_in[8];
    const float* n2b    = (const float*)d_in[9];
    const float* fc1_w  = (const float*)d_in[10];
    const float* fc1_b  = (const float*)d_in[11];
    const float* fc2_w  = (const float*)d_in[12];
    const float* fc2_b  = (const float*)d_in[13];
    float* out = (float*)d_out;

    cudaFuncSetAttribute(gemm_mma<0>, cudaFuncAttributeMaxDynamicSharedMemorySize, GEMM_SMEM_1);
    cudaFuncSetAttribute(gemm_mma<1>, cudaFuncAttributeMaxDynamicSharedMemorySize, GEMM_SMEM_1);
    cudaFuncSetAttribute(gemm_mma<2>, cudaFuncAttributeMaxDynamicSharedMemorySize, GEMM_SMEM_1);
    cudaFuncSetAttribute(gemm_mma<3>, cudaFuncAttributeMaxDynamicSharedMemorySize, GEMM_SMEM_2);
    cudaFuncSetAttribute(attn_mma, cudaFuncAttributeMaxDynamicSharedMemorySize, ATTN_SMEM);

    prep_kernel<<<(24 * NTOK * SBROW + 255) / 256, 256>>>(qkv_w, proj_w, fc1_w, fc2_w, rpb);

    ln_kernel<<<LTOK / 8, 256>>>(x, n1g, n1b);

    gemm_mma<0><<<dim3(3, 686), 256, GEMM_SMEM_1>>>(qkv_b, nullptr, nullptr, 96, nullptr, nullptr);

    attn_mma<<<NWIN * NHEAD, 352, ATTN_SMEM>>>(rpb);

    gemm_mma<1><<<dim3(1, 686), 256, GEMM_SMEM_1>>>(proj_b, x, nullptr, 96, n2g, n2b);

    gemm_mma<2><<<dim3(4, 686), 256, GEMM_SMEM_1>>>(fc1_b, nullptr, nullptr, 96, nullptr, nullptr);

    gemm_mma<3><<<dim3(1, 686), 256, GEMM_SMEM_2>>>(fc2_b, nullptr, out, 384, nullptr, nullptr);
}